// round 1
// baseline (speedup 1.0000x reference)
#include <cuda_runtime.h>
#include <cstdint>

// Problem constants (fixed by the dataset)
#define H    256
#define NMAX 8192
#define EMAX 8192

// ---------------- scratch (static __device__ — no allocations) ----------------
__device__ uint32_t g_bits[(size_t)NMAX * (NMAX / 32)];   // 8 MB packed adjacency
__device__ float    g_Y[(size_t)NMAX * 2 * H];            // 16 MB: [n, 0:256]=x@Wi+bi, [n,256:512]=x@Wj+bj
__device__ float    g_s2[NMAX];                           // s2[n] = x2[n]·vcn
__device__ float    g_vcn[H];                             // Wcn @ ws
__device__ float    g_vf[H];                              // Wf  @ ws
__device__ float    g_ws2[H];                             // vcn + Wlin @ vcn
__device__ float    g_consts[4];                          // [0]=bcn·ws, [1]=bf·ws+bs, [2]=blin·vcn

// ---------------- helpers ----------------
__device__ __forceinline__ float warp_red(float v) {
#pragma unroll
    for (int o = 16; o; o >>= 1) v += __shfl_xor_sync(0xffffffffu, v, o);
    return v;
}

__device__ __forceinline__ float warp_dot256(const float* __restrict__ row,
                                             const float* __restrict__ vec, int lane) {
    float s = 0.f;
#pragma unroll
    for (int c = 0; c < H; c += 32) s = fmaf(row[c + lane], vec[c + lane], s);
    return warp_red(s);
}

// ---------------- K0a: vcn = Wcn@ws, vf = Wf@ws ----------------
__global__ void __launch_bounds__(256) k0a_kernel(const float* __restrict__ Wcn,
                                                  const float* __restrict__ Wf,
                                                  const float* __restrict__ ws) {
    int gw = (blockIdx.x * blockDim.x + threadIdx.x) >> 5;
    int lane = threadIdx.x & 31;
    if (gw < H) {
        float d = warp_dot256(Wcn + (size_t)gw * H, ws, lane);
        if (!lane) g_vcn[gw] = d;
    } else if (gw < 2 * H) {
        int r = gw - H;
        float d = warp_dot256(Wf + (size_t)r * H, ws, lane);
        if (!lane) g_vf[r] = d;
    }
}

// ---------------- K0b: ws2 = vcn + Wlin@vcn, scalar constants ----------------
__global__ void __launch_bounds__(256) k0b_kernel(const float* __restrict__ Wlin,
                                                  const float* __restrict__ blin,
                                                  const float* __restrict__ bcn,
                                                  const float* __restrict__ bf,
                                                  const float* __restrict__ ws,
                                                  const float* __restrict__ bs) {
    int gw = (blockIdx.x * blockDim.x + threadIdx.x) >> 5;
    int lane = threadIdx.x & 31;
    if (gw < H) {
        float d = warp_dot256(Wlin + (size_t)gw * H, g_vcn, lane);
        if (!lane) g_ws2[gw] = g_vcn[gw] + d;
    } else if (gw == H) {
        float d = warp_dot256(blin, g_vcn, lane);
        if (!lane) g_consts[2] = d;                 // c_s2 = blin·vcn
    } else if (gw == H + 1) {
        float d = warp_dot256(bcn, ws, lane);
        if (!lane) g_consts[0] = d;                 // C1 = bcn·ws
    } else if (gw == H + 2) {
        float d = warp_dot256(bf, ws, lane);
        if (!lane) g_consts[1] = d + bs[0];         // C2 = bf·ws + bs
    }
}

// ---------------- pack: adj (f32 0/1) -> bitmask ----------------
// one warp packs 1024 consecutive floats into 32 words (ballot per 32 floats)
__global__ void __launch_bounds__(256) pack_kernel(const float* __restrict__ adj) {
    int gw = (blockIdx.x * blockDim.x + threadIdx.x) >> 5;
    int lane = threadIdx.x & 31;
    size_t fbase = (size_t)gw * 1024;
    uint32_t myword = 0;
#pragma unroll
    for (int i = 0; i < 32; i++) {
        float v = adj[fbase + (size_t)i * 32 + lane];
        uint32_t b = __ballot_sync(0xffffffffu, v != 0.0f);
        if (lane == i) myword = b;
    }
    g_bits[(size_t)gw * 32 + lane] = myword;
}

// ---------------- s2: GEMV s2[n] = x[n]·ws2 + c_s2 ----------------
__global__ void __launch_bounds__(256) s2_kernel(const float* __restrict__ x, int nnodes) {
    int gw = (blockIdx.x * blockDim.x + threadIdx.x) >> 5;
    int lane = threadIdx.x & 31;
    if (gw >= nnodes) return;
    float d = warp_dot256(x + (size_t)gw * H, g_ws2, lane);
    if (!lane) g_s2[gw] = d + g_consts[2];
}

// ---------------- GEMM: Y[n, 0:512] = x @ [Wi | Wj] + [bi | bj] ----------------
#define BM 128
#define BN 128
#define BK 8
#define TM 8
#define TN 8
__global__ void __launch_bounds__(256) gemm_kernel(const float* __restrict__ X,
                                                   const float* __restrict__ Wi,
                                                   const float* __restrict__ Wj,
                                                   const float* __restrict__ bi,
                                                   const float* __restrict__ bj) {
    __shared__ float As[BK][BM];
    __shared__ float Bs[BK][BN];

    int bx = blockIdx.x;            // 0..3  (column block of the 512-wide output)
    int by = blockIdx.y;            // 0..N/128-1
    int tid = threadIdx.x;

    int colbase = bx * BN;          // 0,128,256,384
    const float* W;
    const float* bias;
    if (colbase < H) { W = Wi; bias = bi; }
    else             { W = Wj; bias = bj; colbase -= H; }   // colbase in {0,128}

    // load mappings
    int ar = tid >> 1;              // A row within tile [0,128)
    int ak = (tid & 1) * 4;         // A k-offset {0,4}
    int br = tid >> 5;              // B row (k) within tile [0,8)
    int bc = (tid & 31) * 4;        // B col within tile

    int tx = tid & 15;              // micro-tile col group
    int ty = tid >> 4;              // micro-tile row group

    const float* Arow = X + (size_t)(by * BM + ar) * H;

    float acc[TM][TN];
#pragma unroll
    for (int i = 0; i < TM; i++)
#pragma unroll
        for (int j = 0; j < TN; j++) acc[i][j] = 0.f;

    for (int k0 = 0; k0 < H; k0 += BK) {
        float4 av = *(const float4*)(Arow + k0 + ak);
        As[ak + 0][ar] = av.x;
        As[ak + 1][ar] = av.y;
        As[ak + 2][ar] = av.z;
        As[ak + 3][ar] = av.w;
        float4 bv = *(const float4*)(W + (size_t)(k0 + br) * H + colbase + bc);
        *(float4*)&Bs[br][bc] = bv;
        __syncthreads();

#pragma unroll
        for (int k = 0; k < BK; k++) {
            float4 a0 = *(const float4*)&As[k][ty * TM];
            float4 a1 = *(const float4*)&As[k][ty * TM + 4];
            float4 b0 = *(const float4*)&Bs[k][tx * TN];
            float4 b1 = *(const float4*)&Bs[k][tx * TN + 4];
            float a[TM] = {a0.x, a0.y, a0.z, a0.w, a1.x, a1.y, a1.z, a1.w};
            float b[TN] = {b0.x, b0.y, b0.z, b0.w, b1.x, b1.y, b1.z, b1.w};
#pragma unroll
            for (int i = 0; i < TM; i++)
#pragma unroll
                for (int j = 0; j < TN; j++) acc[i][j] = fmaf(a[i], b[j], acc[i][j]);
        }
        __syncthreads();
    }

#pragma unroll
    for (int i = 0; i < TM; i++) {
        int row = by * BM + ty * TM + i;
        float* orow = g_Y + (size_t)row * (2 * H) + bx * BN;
#pragma unroll
        for (int j = 0; j < TN; j += 4) {
            int col = tx * TN + j;
            float4 o;
            o.x = acc[i][j + 0] + bias[colbase + col + 0];
            o.y = acc[i][j + 1] + bias[colbase + col + 1];
            o.z = acc[i][j + 2] + bias[colbase + col + 2];
            o.w = acc[i][j + 3] + bias[colbase + col + 3];
            *(float4*)(orow + col) = o;
        }
    }
}

// ---------------- edge kernel: one warp per edge ----------------
__global__ void __launch_bounds__(256) edge_kernel(const int* __restrict__ tei, int E, int nwords,
                                                   const float* __restrict__ beta_p,
                                                   const int* __restrict__ boolen_p,
                                                   float* __restrict__ out) {
    int gw = (blockIdx.x * blockDim.x + threadIdx.x) >> 5;
    int lane = threadIdx.x & 31;
    if (gw >= E) return;

    int src = tei[gw];
    int dst = tei[E + gw];

    // common-neighbor weighted count: sum of s2 over AND of bit rows
    const uint32_t* bsrc = g_bits + (size_t)src * nwords;
    const uint32_t* bdst = g_bits + (size_t)dst * nwords;
    float s = 0.f;
    for (int w = lane; w < nwords; w += 32) {
        uint32_t a = bsrc[w] & bdst[w];
        while (a) {
            int b = __ffs(a) - 1;
            a &= a - 1;
            s += g_s2[w * 32 + b];
        }
    }

    // t = relu(yi[src] + yj[dst]) · vf
    const float* pyi = g_Y + (size_t)src * (2 * H);
    const float* pyj = g_Y + (size_t)dst * (2 * H) + H;
    float t = 0.f;
#pragma unroll
    for (int c = 0; c < H; c += 32) {
        float z = pyi[c + lane] + pyj[c + lane];
        z = fmaxf(z, 0.f);
        t = fmaf(z, g_vf[c + lane], t);
    }

    float beta = beta_p[0];
    float val = warp_red(t + beta * s);
    if (!lane) {
        float u = val + beta * g_consts[0] + g_consts[1];
        bool pos = boolen_p ? (boolen_p[0] != 0) : true;
        float v = pos ? u : -u;
        // -log_sigmoid(v) = softplus(-v), numerically stable
        out[gw] = fmaxf(-v, 0.f) + log1pf(expf(-fabsf(v)));
    }
}

// ---------------- launch ----------------
extern "C" void kernel_launch(void* const* d_in, const int* in_sizes, int n_in,
                              void* d_out, int out_size) {
    const float* x    = (const float*)d_in[0];
    const float* adj  = (const float*)d_in[1];
    const int*   tei  = (const int*)d_in[2];
    const float* Wlin = (const float*)d_in[3];
    const float* blin = (const float*)d_in[4];
    const float* Wcn  = (const float*)d_in[5];
    const float* bcn  = (const float*)d_in[6];
    const float* Wi   = (const float*)d_in[7];
    const float* bi   = (const float*)d_in[8];
    const float* Wj   = (const float*)d_in[9];
    const float* bj   = (const float*)d_in[10];
    const float* Wf   = (const float*)d_in[11];
    const float* bf   = (const float*)d_in[12];
    const float* ws   = (const float*)d_in[13];
    const float* bs   = (const float*)d_in[14];
    const float* beta = (const float*)d_in[15];
    const int* boolen = (n_in > 16) ? (const int*)d_in[16] : nullptr;
    float* out = (float*)d_out;

    const int N = in_sizes[0] / H;   // 8192 nodes
    const int E = in_sizes[2] / 2;   // 8192 edges
    const int nwords = N / 32;       // 256 words per adjacency row

    // 1) pack adjacency to bits: N*N floats, 1024 per warp, 8 warps per block
    {
        long long warps = (long long)N * N / 1024;
        int blocks = (int)((warps + 7) / 8);
        pack_kernel<<<blocks, 256>>>(adj);
    }
    // 2) fold the 1-wide head through the linear layers
    k0a_kernel<<<(2 * H + 7) / 8, 256>>>(Wcn, Wf, ws);
    k0b_kernel<<<(H + 3 + 7) / 8, 256>>>(Wlin, blin, bcn, bf, ws, bs);
    // 3) s2[n] = x2[n]·vcn  (GEMV, replaces the x2 GEMM + SpMM entirely)
    s2_kernel<<<(N + 7) / 8, 256>>>(x, N);
    // 4) the only real GEMM: Y = x @ [Wi|Wj] + [bi|bj]   (8192 x 512 x 256)
    gemm_kernel<<<dim3(4, N / BM), 256>>>(x, Wi, Wj, bi, bj);
    // 5) per-edge: CN bit-AND gather + relu-dot + logsigmoid
    edge_kernel<<<(E + 7) / 8, 256>>>(tei, E, nwords, beta, boolen, out);
}

// round 2
// speedup vs baseline: 1.0797x; 1.0797x over previous
#include <cuda_runtime.h>
#include <cstdint>

// Problem constants (fixed by the dataset)
#define H    256
#define NMAX 8192

// ---------------- scratch (static __device__ — no allocations) ----------------
__device__ uint32_t g_bits[(size_t)NMAX * (NMAX / 32)];   // 8 MB packed adjacency
__device__ float    g_Y[(size_t)NMAX * 2 * H];            // 16 MB: [n,0:256]=x@Wi+bi, [n,256:512]=x@Wj+bj
__device__ float    g_s2[NMAX];                           // s2[n] = x2[n]·vcn
__device__ float    g_vcn[H];                             // Wcn @ ws
__device__ float    g_vf[H];                              // Wf  @ ws
__device__ float    g_ws2[H];                             // vcn + Wlin @ vcn
__device__ float    g_consts[4];                          // [0]=bcn·ws, [1]=bf·ws+bs, [2]=blin·vcn

// ---------------- helpers ----------------
__device__ __forceinline__ float warp_red(float v) {
#pragma unroll
    for (int o = 16; o; o >>= 1) v += __shfl_xor_sync(0xffffffffu, v, o);
    return v;
}

__device__ __forceinline__ float warp_dot256(const float* __restrict__ row,
                                             const float* __restrict__ vec, int lane) {
    float s = 0.f;
#pragma unroll
    for (int c = 0; c < H; c += 32) s = fmaf(row[c + lane], vec[c + lane], s);
    return warp_red(s);
}

// ---------------- K0a: vcn = Wcn@ws, vf = Wf@ws ----------------
__global__ void __launch_bounds__(256) k0a_kernel(const float* __restrict__ Wcn,
                                                  const float* __restrict__ Wf,
                                                  const float* __restrict__ ws) {
    int gw = (blockIdx.x * blockDim.x + threadIdx.x) >> 5;
    int lane = threadIdx.x & 31;
    if (gw < H) {
        float d = warp_dot256(Wcn + (size_t)gw * H, ws, lane);
        if (!lane) g_vcn[gw] = d;
    } else if (gw < 2 * H) {
        int r = gw - H;
        float d = warp_dot256(Wf + (size_t)r * H, ws, lane);
        if (!lane) g_vf[r] = d;
    }
}

// ---------------- K0b: ws2 = vcn + Wlin@vcn, scalar constants ----------------
__global__ void __launch_bounds__(256) k0b_kernel(const float* __restrict__ Wlin,
                                                  const float* __restrict__ blin,
                                                  const float* __restrict__ bcn,
                                                  const float* __restrict__ bf,
                                                  const float* __restrict__ ws,
                                                  const float* __restrict__ bs) {
    int gw = (blockIdx.x * blockDim.x + threadIdx.x) >> 5;
    int lane = threadIdx.x & 31;
    if (gw < H) {
        float d = warp_dot256(Wlin + (size_t)gw * H, g_vcn, lane);
        if (!lane) g_ws2[gw] = g_vcn[gw] + d;
    } else if (gw == H) {
        float d = warp_dot256(blin, g_vcn, lane);
        if (!lane) g_consts[2] = d;                 // c_s2 = blin·vcn
    } else if (gw == H + 1) {
        float d = warp_dot256(bcn, ws, lane);
        if (!lane) g_consts[0] = d;                 // C1 = bcn·ws
    } else if (gw == H + 2) {
        float d = warp_dot256(bf, ws, lane);
        if (!lane) g_consts[1] = d + bs[0];         // C2 = bf·ws + bs
    }
}

// ---------------- role bodies for the fused kernel ----------------

// pack: one warp packs 1024 consecutive adj floats into 32 bit-words.
// Loads are front-batched (MLP_p1 = 32) so the warp keeps the DRAM queue full.
__device__ __forceinline__ void pack_warp(const float* __restrict__ adj,
                                          size_t gw, int lane) {
    size_t fbase = gw * 1024;
    float v[32];
#pragma unroll
    for (int i = 0; i < 32; i++) v[i] = adj[fbase + (size_t)i * 32 + lane];
    uint32_t myword = 0;
#pragma unroll
    for (int i = 0; i < 32; i++) {
        uint32_t b = __ballot_sync(0xffffffffu, v[i] != 0.0f);
        if (lane == i) myword = b;
    }
    g_bits[gw * 32 + lane] = myword;
}

// GEMM tile: Y[by*128 .. , bx*128 ..] for Y = x @ [Wi|Wj] + [bi|bj]
#define BM 128
#define BN 128
#define BK 8
#define TM 8
#define TN 8
__device__ __forceinline__ void gemm_block(int bx, int by,
                                           const float* __restrict__ X,
                                           const float* __restrict__ Wi,
                                           const float* __restrict__ Wj,
                                           const float* __restrict__ bi,
                                           const float* __restrict__ bj,
                                           float* As /*[BK][BM]*/,
                                           float* Bs /*[BK][BN]*/) {
    int tid = threadIdx.x;

    int colbase = bx * BN;          // 0,128,256,384
    const float* W;
    const float* bias;
    if (colbase < H) { W = Wi; bias = bi; }
    else             { W = Wj; bias = bj; colbase -= H; }

    int ar = tid >> 1;              // A row within tile [0,128)
    int ak = (tid & 1) * 4;         // A k-offset {0,4}
    int br = tid >> 5;              // B row (k) within tile [0,8)
    int bc = (tid & 31) * 4;        // B col within tile

    int tx = tid & 15;
    int ty = tid >> 4;

    const float* Arow = X + (size_t)(by * BM + ar) * H;

    float acc[TM][TN];
#pragma unroll
    for (int i = 0; i < TM; i++)
#pragma unroll
        for (int j = 0; j < TN; j++) acc[i][j] = 0.f;

    for (int k0 = 0; k0 < H; k0 += BK) {
        float4 av = *(const float4*)(Arow + k0 + ak);
        As[(ak + 0) * BM + ar] = av.x;
        As[(ak + 1) * BM + ar] = av.y;
        As[(ak + 2) * BM + ar] = av.z;
        As[(ak + 3) * BM + ar] = av.w;
        float4 bv = *(const float4*)(W + (size_t)(k0 + br) * H + colbase + bc);
        *(float4*)&Bs[br * BN + bc] = bv;
        __syncthreads();

#pragma unroll
        for (int k = 0; k < BK; k++) {
            float4 a0 = *(const float4*)&As[k * BM + ty * TM];
            float4 a1 = *(const float4*)&As[k * BM + ty * TM + 4];
            float4 b0 = *(const float4*)&Bs[k * BN + tx * TN];
            float4 b1 = *(const float4*)&Bs[k * BN + tx * TN + 4];
            float a[TM] = {a0.x, a0.y, a0.z, a0.w, a1.x, a1.y, a1.z, a1.w};
            float b[TN] = {b0.x, b0.y, b0.z, b0.w, b1.x, b1.y, b1.z, b1.w};
#pragma unroll
            for (int i = 0; i < TM; i++)
#pragma unroll
                for (int j = 0; j < TN; j++) acc[i][j] = fmaf(a[i], b[j], acc[i][j]);
        }
        __syncthreads();
    }

#pragma unroll
    for (int i = 0; i < TM; i++) {
        int row = by * BM + ty * TM + i;
        float* orow = g_Y + (size_t)row * (2 * H) + bx * BN;
#pragma unroll
        for (int j = 0; j < TN; j += 4) {
            int col = tx * TN + j;
            float4 o;
            o.x = acc[i][j + 0] + bias[colbase + col + 0];
            o.y = acc[i][j + 1] + bias[colbase + col + 1];
            o.z = acc[i][j + 2] + bias[colbase + col + 2];
            o.w = acc[i][j + 3] + bias[colbase + col + 3];
            *(float4*)(orow + col) = o;
        }
    }
}

// ---------------- fused kernel: pack ∪ GEMM ∪ s2, role by blockIdx ----------------
// Block roles interleaved so wave-1 co-schedules GEMM (FMA-bound) with pack
// (DRAM-bound) on every SM:
//   bid in [0, 2*nbGemm): even -> gemm(bid/2), odd -> pack(bid/2)
//   bid in [2*nbGemm, 2*nbGemm + nbS2): s2
//   rest: pack (ids continuing from nbGemm)
__global__ void __launch_bounds__(256, 2) fused_kernel(const float* __restrict__ x,
                                                       const float* __restrict__ adj,
                                                       const float* __restrict__ Wi,
                                                       const float* __restrict__ Wj,
                                                       const float* __restrict__ bi,
                                                       const float* __restrict__ bj,
                                                       int N) {
    __shared__ float smem[BK * BM + BK * BN];

    const int nbGemm = (N / BM) * 4;      // 256
    const int nbS2   = N / 8;             // 1024
    int bid = blockIdx.x;
    int warp = threadIdx.x >> 5;
    int lane = threadIdx.x & 31;

    if (bid < 2 * nbGemm) {
        int half = bid >> 1;
        if ((bid & 1) == 0) {
            // GEMM role
            int bx = half & 3;
            int by = half >> 2;
            gemm_block(bx, by, x, Wi, Wj, bi, bj, smem, smem + BK * BM);
        } else {
            // pack role (first nbGemm pack ids)
            size_t gw = (size_t)half * 8 + warp;
            pack_warp(adj, gw, lane);
        }
    } else if (bid < 2 * nbGemm + nbS2) {
        // s2 role: one warp per node
        int sb = bid - 2 * nbGemm;
        int node = sb * 8 + warp;
        if (node < N) {
            float d = warp_dot256(x + (size_t)node * H, g_ws2, lane);
            if (!lane) g_s2[node] = d + g_consts[2];
        }
    } else {
        // pack role (remaining ids)
        int pb = nbGemm + (bid - 2 * nbGemm - nbS2);
        size_t gw = (size_t)pb * 8 + warp;
        pack_warp(adj, gw, lane);
    }
}

// ---------------- edge kernel: one warp per edge ----------------
__global__ void __launch_bounds__(256) edge_kernel(const int* __restrict__ tei, int E, int nwords,
                                                   const float* __restrict__ beta_p,
                                                   const int* __restrict__ boolen_p,
                                                   float* __restrict__ out) {
    int gw = (blockIdx.x * blockDim.x + threadIdx.x) >> 5;
    int lane = threadIdx.x & 31;
    if (gw >= E) return;

    int src = tei[gw];
    int dst = tei[E + gw];

    // common-neighbor weighted count: sum of s2 over AND of bit rows
    const uint32_t* bsrc = g_bits + (size_t)src * nwords;
    const uint32_t* bdst = g_bits + (size_t)dst * nwords;
    float s = 0.f;
    for (int w = lane; w < nwords; w += 32) {
        uint32_t a = bsrc[w] & bdst[w];
        while (a) {
            int b = __ffs(a) - 1;
            a &= a - 1;
            s += g_s2[w * 32 + b];
        }
    }

    // t = relu(yi[src] + yj[dst]) · vf
    const float* pyi = g_Y + (size_t)src * (2 * H);
    const float* pyj = g_Y + (size_t)dst * (2 * H) + H;
    float t = 0.f;
#pragma unroll
    for (int c = 0; c < H; c += 32) {
        float z = pyi[c + lane] + pyj[c + lane];
        z = fmaxf(z, 0.f);
        t = fmaf(z, g_vf[c + lane], t);
    }

    float beta = beta_p[0];
    float val = warp_red(t + beta * s);
    if (!lane) {
        float u = val + beta * g_consts[0] + g_consts[1];
        bool pos = boolen_p ? (boolen_p[0] != 0) : true;
        float v = pos ? u : -u;
        // -log_sigmoid(v) = softplus(-v), numerically stable
        out[gw] = fmaxf(-v, 0.f) + log1pf(expf(-fabsf(v)));
    }
}

// ---------------- launch ----------------
extern "C" void kernel_launch(void* const* d_in, const int* in_sizes, int n_in,
                              void* d_out, int out_size) {
    const float* x    = (const float*)d_in[0];
    const float* adj  = (const float*)d_in[1];
    const int*   tei  = (const int*)d_in[2];
    const float* Wlin = (const float*)d_in[3];
    const float* blin = (const float*)d_in[4];
    const float* Wcn  = (const float*)d_in[5];
    const float* bcn  = (const float*)d_in[6];
    const float* Wi   = (const float*)d_in[7];
    const float* bi   = (const float*)d_in[8];
    const float* Wj   = (const float*)d_in[9];
    const float* bj   = (const float*)d_in[10];
    const float* Wf   = (const float*)d_in[11];
    const float* bf   = (const float*)d_in[12];
    const float* ws   = (const float*)d_in[13];
    const float* bs   = (const float*)d_in[14];
    const float* beta = (const float*)d_in[15];
    const int* boolen = (n_in > 16) ? (const int*)d_in[16] : nullptr;
    float* out = (float*)d_out;

    const int N = in_sizes[0] / H;   // 8192 nodes
    const int E = in_sizes[2] / 2;   // 8192 edges
    const int nwords = N / 32;       // 256 words per adjacency row

    // 1) fold the 1-wide head through the linear layers (tiny, sequential deps)
    k0a_kernel<<<(2 * H + 7) / 8, 256>>>(Wcn, Wf, ws);
    k0b_kernel<<<(H + 3 + 7) / 8, 256>>>(Wlin, blin, bcn, bf, ws, bs);

    // 2) ONE fused launch: adjacency pack (DRAM-bound) + GEMM (FMA-bound) + s2,
    //    block roles interleaved for co-residency on every SM.
    {
        int nbGemm = (N / BM) * 4;                       // 256
        int nbS2   = N / 8;                              // 1024
        long long packWarps = (long long)N * N / 1024;   // 65536
        int nbPack = (int)(packWarps / 8);               // 8192
        int total = nbGemm + nbS2 + nbPack;              // 9472
        fused_kernel<<<total, 256>>>(x, adj, Wi, Wj, bi, bj, N);
    }

    // 3) per-edge: CN bit-AND gather + relu-dot + logsigmoid
    edge_kernel<<<(E + 7) / 8, 256>>>(tei, E, nwords, beta, boolen, out);
}

// round 3
// speedup vs baseline: 1.1560x; 1.0707x over previous
#include <cuda_runtime.h>
#include <cuda_bf16.h>
#include <cstdint>

// Problem constants (fixed by the dataset)
#define H    256
#define NMAX 8192
#define EMAX 8192
#define KTOT 512            // concatenated K dim: [xi | xj]

// ---------------- scratch (static __device__ — no allocations) ----------------
__device__ uint32_t      g_bits[(size_t)NMAX * (NMAX / 32)];  // 8 MB packed adjacency
__device__ __nv_bfloat16 g_Xhi[(size_t)NMAX * H];             // 4 MB bf16 hi of x
__device__ __nv_bfloat16 g_Xlo[(size_t)NMAX * H];             // 4 MB bf16 lo of x
__device__ __nv_bfloat16 g_Wthi[(size_t)H * KTOT];            // 256 KB: Wt[n][k] hi, k<256 -> Wi, else Wj
__device__ __nv_bfloat16 g_Wtlo[(size_t)H * KTOT];            // 256 KB
__device__ float         g_t[EMAX];                           // per-edge relu(Z)·vf
__device__ float         g_s2[NMAX];                          // s2[n] = x2[n]·vcn
__device__ float         g_vcn[H];                            // Wcn @ ws
__device__ float         g_vf[H];                             // Wf  @ ws
__device__ float         g_ws2[H];                            // vcn + Wlin @ vcn
__device__ float         g_consts[4];                         // [0]=bcn·ws, [1]=bf·ws+bs, [2]=blin·vcn

// ---------------- helpers ----------------
__device__ __forceinline__ float warp_red(float v) {
#pragma unroll
    for (int o = 16; o; o >>= 1) v += __shfl_xor_sync(0xffffffffu, v, o);
    return v;
}

__device__ __forceinline__ float warp_dot256(const float* __restrict__ row,
                                             const float* __restrict__ vec, int lane) {
    float s = 0.f;
#pragma unroll
    for (int c = 0; c < H; c += 32) s = fmaf(row[c + lane], vec[c + lane], s);
    return warp_red(s);
}

__device__ __forceinline__ void mma16816(float c[4], uint32_t a0, uint32_t a1,
                                         uint32_t a2, uint32_t a3,
                                         uint32_t b0, uint32_t b1) {
    asm volatile(
        "mma.sync.aligned.m16n8k16.row.col.f32.bf16.bf16.f32 "
        "{%0,%1,%2,%3}, {%4,%5,%6,%7}, {%8,%9}, {%0,%1,%2,%3};"
        : "+f"(c[0]), "+f"(c[1]), "+f"(c[2]), "+f"(c[3])
        : "r"(a0), "r"(a1), "r"(a2), "r"(a3), "r"(b0), "r"(b1));
}

// ---------------- prep: split x -> (Xhi, Xlo), build Wt = [Wi;Wj]^T hi/lo ----------------
__global__ void __launch_bounds__(256) prep_kernel(const float* __restrict__ x,
                                                   const float* __restrict__ Wi,
                                                   const float* __restrict__ Wj) {
    int bid = blockIdx.x;
    int tid = threadIdx.x;
    if (bid < (NMAX * H) / 1024) {
        // x conversion: one float4 per thread
        int gid = bid * 256 + tid;
        float4 v = ((const float4*)x)[gid];
        __nv_bfloat16 hx = __float2bfloat16(v.x), hy = __float2bfloat16(v.y);
        __nv_bfloat16 hz = __float2bfloat16(v.z), hw = __float2bfloat16(v.w);
        __nv_bfloat16 lx = __float2bfloat16(v.x - __bfloat162float(hx));
        __nv_bfloat16 ly = __float2bfloat16(v.y - __bfloat162float(hy));
        __nv_bfloat16 lz = __float2bfloat16(v.z - __bfloat162float(hz));
        __nv_bfloat16 lw = __float2bfloat16(v.w - __bfloat162float(hw));
        ((__nv_bfloat162*)g_Xhi)[gid * 2 + 0] = __nv_bfloat162(hx, hy);
        ((__nv_bfloat162*)g_Xhi)[gid * 2 + 1] = __nv_bfloat162(hz, hw);
        ((__nv_bfloat162*)g_Xlo)[gid * 2 + 0] = __nv_bfloat162(lx, ly);
        ((__nv_bfloat162*)g_Xlo)[gid * 2 + 1] = __nv_bfloat162(lz, lw);
    } else {
        // W transpose+split: one n-column per block
        int n = bid - (NMAX * H) / 1024;
        if (n >= H) return;
        for (int k = tid; k < KTOT; k += 256) {
            float w = (k < H) ? Wi[(size_t)k * H + n] : Wj[(size_t)(k - H) * H + n];
            __nv_bfloat16 hi = __float2bfloat16(w);
            __nv_bfloat16 lo = __float2bfloat16(w - __bfloat162float(hi));
            g_Wthi[(size_t)n * KTOT + k] = hi;
            g_Wtlo[(size_t)n * KTOT + k] = lo;
        }
    }
}

// ---------------- K0a: vcn = Wcn@ws, vf = Wf@ws ----------------
__global__ void __launch_bounds__(256) k0a_kernel(const float* __restrict__ Wcn,
                                                  const float* __restrict__ Wf,
                                                  const float* __restrict__ ws) {
    int gw = (blockIdx.x * blockDim.x + threadIdx.x) >> 5;
    int lane = threadIdx.x & 31;
    if (gw < H) {
        float d = warp_dot256(Wcn + (size_t)gw * H, ws, lane);
        if (!lane) g_vcn[gw] = d;
    } else if (gw < 2 * H) {
        int r = gw - H;
        float d = warp_dot256(Wf + (size_t)r * H, ws, lane);
        if (!lane) g_vf[r] = d;
    }
}

// ---------------- K0b: ws2 = vcn + Wlin@vcn, scalar constants ----------------
__global__ void __launch_bounds__(256) k0b_kernel(const float* __restrict__ Wlin,
                                                  const float* __restrict__ blin,
                                                  const float* __restrict__ bcn,
                                                  const float* __restrict__ bf,
                                                  const float* __restrict__ ws,
                                                  const float* __restrict__ bs) {
    int gw = (blockIdx.x * blockDim.x + threadIdx.x) >> 5;
    int lane = threadIdx.x & 31;
    if (gw < H) {
        float d = warp_dot256(Wlin + (size_t)gw * H, g_vcn, lane);
        if (!lane) g_ws2[gw] = g_vcn[gw] + d;
    } else if (gw == H) {
        float d = warp_dot256(blin, g_vcn, lane);
        if (!lane) g_consts[2] = d;
    } else if (gw == H + 1) {
        float d = warp_dot256(bcn, ws, lane);
        if (!lane) g_consts[0] = d;
    } else if (gw == H + 2) {
        float d = warp_dot256(bf, ws, lane);
        if (!lane) g_consts[1] = d + bs[0];
    }
}

// ---------------- pack body: one warp packs 1024 adj floats -> 32 bit-words ----------------
__device__ __forceinline__ void pack_warp(const float* __restrict__ adj,
                                          size_t gw, int lane) {
    size_t fbase = gw * 1024;
    float v[32];
#pragma unroll
    for (int i = 0; i < 32; i++) v[i] = adj[fbase + (size_t)i * 32 + lane];
    uint32_t myword = 0;
#pragma unroll
    for (int i = 0; i < 32; i++) {
        uint32_t b = __ballot_sync(0xffffffffu, v[i] != 0.0f);
        if (lane == i) myword = b;
    }
    g_bits[gw * 32 + lane] = myword;
}

// ---------------- tensor-core edge GEMM body ----------------
// 64 edges x 256 cols, K = 512 ([xi | xj]); split-bf16 3-pass (hi*hi + hi*lo + lo*hi).
// Epilogue computes t[e] = sum_c relu(Z[e,c] + bi[c]+bj[c]) * vf[c] in-register.
// SMEM fragment tiles padded to 12 words/row -> bank-conflict-free LDS.
#define ROWPAD 12      // 16 bf16 (8 words) padded to 12 words
__device__ __forceinline__ void gemm_block(int gb, const int* __restrict__ tei, int E,
                                           const float* __restrict__ bi,
                                           const float* __restrict__ bj,
                                           uint32_t* smem) {
    uint32_t* AsHi = smem;                 // 64*12
    uint32_t* AsLo = smem + 768;           // 64*12
    uint32_t* BsHi = smem + 1536;          // 256*12
    uint32_t* BsLo = smem + 4608;          // 256*12
    float*    tsum = (float*)(smem + 7680); // [2][64]
    int*      eidx = (int*)(smem + 7808);   // [2][64] src, dst

    int tid = threadIdx.x;
    int lane = tid & 31, wid = tid >> 5;
    int wm = wid & 3, wn = wid >> 2;       // 4 m-groups x 2 n-groups
    int ebase = gb * 64;

    if (tid < 64) {
        eidx[tid]      = tei[ebase + tid];
        eidx[64 + tid] = tei[E + ebase + tid];
    }
    __syncthreads();

    float acc[16][4];
#pragma unroll
    for (int j = 0; j < 16; j++)
#pragma unroll
        for (int q = 0; q < 4; q++) acc[j][q] = 0.f;

    int arow = tid >> 2;                   // A-load row per thread
    int aq   = tid & 3;                    // A-load quad (4 bf16)

    for (int ks = 0; ks < KTOT / 16; ks++) {
        int k0 = ks * 16;
        // --- load A tile (64 x 16, hi+lo) gathered by edge endpoint ---
        {
            int node = eidx[(k0 < H ? 0 : 64) + arow];
            int gc = (k0 & (H - 1)) + aq * 4;
            uint2 vh = *(const uint2*)(g_Xhi + (size_t)node * H + gc);
            uint2 vl = *(const uint2*)(g_Xlo + (size_t)node * H + gc);
            AsHi[arow * ROWPAD + aq * 2 + 0] = vh.x;
            AsHi[arow * ROWPAD + aq * 2 + 1] = vh.y;
            AsLo[arow * ROWPAD + aq * 2 + 0] = vl.x;
            AsLo[arow * ROWPAD + aq * 2 + 1] = vl.y;
        }
        // --- load B tile (256 n x 16 k, hi+lo): one n-row per thread ---
        {
            const uint4* ph = (const uint4*)(g_Wthi + (size_t)tid * KTOT + k0);
            uint4 h0 = ph[0], h1 = ph[1];
            BsHi[tid * ROWPAD + 0] = h0.x; BsHi[tid * ROWPAD + 1] = h0.y;
            BsHi[tid * ROWPAD + 2] = h0.z; BsHi[tid * ROWPAD + 3] = h0.w;
            BsHi[tid * ROWPAD + 4] = h1.x; BsHi[tid * ROWPAD + 5] = h1.y;
            BsHi[tid * ROWPAD + 6] = h1.z; BsHi[tid * ROWPAD + 7] = h1.w;
            const uint4* pl = (const uint4*)(g_Wtlo + (size_t)tid * KTOT + k0);
            uint4 l0 = pl[0], l1 = pl[1];
            BsLo[tid * ROWPAD + 0] = l0.x; BsLo[tid * ROWPAD + 1] = l0.y;
            BsLo[tid * ROWPAD + 2] = l0.z; BsLo[tid * ROWPAD + 3] = l0.w;
            BsLo[tid * ROWPAD + 4] = l1.x; BsLo[tid * ROWPAD + 5] = l1.y;
            BsLo[tid * ROWPAD + 6] = l1.z; BsLo[tid * ROWPAD + 7] = l1.w;
        }
        __syncthreads();

        int r0 = wm * 16 + (lane >> 2);
        int w4 = lane & 3;
        uint32_t ah0 = AsHi[r0 * ROWPAD + w4];
        uint32_t ah1 = AsHi[(r0 + 8) * ROWPAD + w4];
        uint32_t ah2 = AsHi[r0 * ROWPAD + w4 + 4];
        uint32_t ah3 = AsHi[(r0 + 8) * ROWPAD + w4 + 4];
        uint32_t al0 = AsLo[r0 * ROWPAD + w4];
        uint32_t al1 = AsLo[(r0 + 8) * ROWPAD + w4];
        uint32_t al2 = AsLo[r0 * ROWPAD + w4 + 4];
        uint32_t al3 = AsLo[(r0 + 8) * ROWPAD + w4 + 4];

#pragma unroll
        for (int j = 0; j < 16; j++) {
            int nr = wn * 128 + j * 8 + (lane >> 2);
            uint32_t bh0 = BsHi[nr * ROWPAD + w4];
            uint32_t bh1 = BsHi[nr * ROWPAD + w4 + 4];
            uint32_t bl0 = BsLo[nr * ROWPAD + w4];
            uint32_t bl1 = BsLo[nr * ROWPAD + w4 + 4];
            mma16816(acc[j], ah0, ah1, ah2, ah3, bh0, bh1);   // hi*hi
            mma16816(acc[j], ah0, ah1, ah2, ah3, bl0, bl1);   // hi*lo
            mma16816(acc[j], al0, al1, al2, al3, bh0, bh1);   // lo*hi
        }
        __syncthreads();
    }

    // --- epilogue: t partials, relu(z + bsum) * vf ---
    float tp0 = 0.f, tp1 = 0.f;
#pragma unroll
    for (int j = 0; j < 16; j++) {
        int col = wn * 128 + j * 8 + (lane & 3) * 2;
        float b0 = bi[col] + bj[col];
        float b1 = bi[col + 1] + bj[col + 1];
        float v0 = g_vf[col], v1 = g_vf[col + 1];
        tp0 += fmaxf(acc[j][0] + b0, 0.f) * v0 + fmaxf(acc[j][1] + b1, 0.f) * v1;
        tp1 += fmaxf(acc[j][2] + b0, 0.f) * v0 + fmaxf(acc[j][3] + b1, 0.f) * v1;
    }
    tp0 += __shfl_xor_sync(0xffffffffu, tp0, 1);
    tp0 += __shfl_xor_sync(0xffffffffu, tp0, 2);
    tp1 += __shfl_xor_sync(0xffffffffu, tp1, 1);
    tp1 += __shfl_xor_sync(0xffffffffu, tp1, 2);
    if ((lane & 3) == 0) {
        int r = wm * 16 + (lane >> 2);
        tsum[wn * 64 + r] = tp0;          // deterministic: unique (wn,row) slots
        tsum[wn * 64 + r + 8] = tp1;
    }
    __syncthreads();
    if (tid < 64) g_t[ebase + tid] = tsum[tid] + tsum[64 + tid];
}

// ---------------- fused kernel: pack ∪ tensor-GEMM ∪ s2 ----------------
__global__ void __launch_bounds__(256) fused_kernel(const float* __restrict__ x,
                                                    const float* __restrict__ adj,
                                                    const int* __restrict__ tei,
                                                    const float* __restrict__ bi,
                                                    const float* __restrict__ bj,
                                                    int N, int E) {
    __shared__ uint32_t smem[7936];   // 31 KB: gemm role only

    const int nbGemm = E / 64;        // 128
    const int nbS2   = N / 8;         // 1024
    int bid = blockIdx.x;
    int warp = threadIdx.x >> 5;
    int lane = threadIdx.x & 31;

    if (bid < 2 * nbGemm) {
        int half = bid >> 1;
        if ((bid & 1) == 0) {
            gemm_block(half, tei, E, bi, bj, smem);
        } else {
            pack_warp(adj, (size_t)half * 8 + warp, lane);
        }
    } else if (bid < 2 * nbGemm + nbS2) {
        int node = (bid - 2 * nbGemm) * 8 + warp;
        if (node < N) {
            float d = warp_dot256(x + (size_t)node * H, g_ws2, lane);
            if (!lane) g_s2[node] = d + g_consts[2];
        }
    } else {
        int pb = nbGemm + (bid - 2 * nbGemm - nbS2);
        pack_warp(adj, (size_t)pb * 8 + warp, lane);
    }
}

// ---------------- final edge kernel: CN bit-AND gather + combine + softplus ----------------
__global__ void __launch_bounds__(256) edge_kernel(const int* __restrict__ tei, int E, int nwords,
                                                   const float* __restrict__ beta_p,
                                                   const int* __restrict__ boolen_p,
                                                   float* __restrict__ out) {
    int gw = (blockIdx.x * blockDim.x + threadIdx.x) >> 5;
    int lane = threadIdx.x & 31;
    if (gw >= E) return;

    int src = tei[gw];
    int dst = tei[E + gw];

    const uint32_t* bsrc = g_bits + (size_t)src * nwords;
    const uint32_t* bdst = g_bits + (size_t)dst * nwords;
    float s = 0.f;
    for (int w = lane; w < nwords; w += 32) {
        uint32_t a = bsrc[w] & bdst[w];
        while (a) {
            int b = __ffs(a) - 1;
            a &= a - 1;
            s += g_s2[w * 32 + b];
        }
    }
    float S = warp_red(s);

    if (!lane) {
        float beta = beta_p[0];
        float u = g_t[gw] + beta * (S + g_consts[0]) + g_consts[1];
        bool pos = boolen_p ? (boolen_p[0] != 0) : true;
        float v = pos ? u : -u;
        out[gw] = fmaxf(-v, 0.f) + log1pf(expf(-fabsf(v)));  // softplus(-v)
    }
}

// ---------------- launch ----------------
extern "C" void kernel_launch(void* const* d_in, const int* in_sizes, int n_in,
                              void* d_out, int out_size) {
    const float* x    = (const float*)d_in[0];
    const float* adj  = (const float*)d_in[1];
    const int*   tei  = (const int*)d_in[2];
    const float* Wlin = (const float*)d_in[3];
    const float* blin = (const float*)d_in[4];
    const float* Wcn  = (const float*)d_in[5];
    const float* bcn  = (const float*)d_in[6];
    const float* Wi   = (const float*)d_in[7];
    const float* bi   = (const float*)d_in[8];
    const float* Wj   = (const float*)d_in[9];
    const float* bj   = (const float*)d_in[10];
    const float* Wf   = (const float*)d_in[11];
    const float* bf   = (const float*)d_in[12];
    const float* ws   = (const float*)d_in[13];
    const float* bs   = (const float*)d_in[14];
    const float* beta = (const float*)d_in[15];
    const int* boolen = (n_in > 16) ? (const int*)d_in[16] : nullptr;
    float* out = (float*)d_out;

    const int N = in_sizes[0] / H;   // 8192 nodes
    const int E = in_sizes[2] / 2;   // 8192 edges
    const int nwords = N / 32;       // 256 words per adjacency row

    // 1) split-precision prep (x -> bf16 hi/lo, W -> transposed bf16 hi/lo)
    prep_kernel<<<(NMAX * H) / 1024 + H, 256>>>(x, Wi, Wj);
    // 2) fold the 1-wide head through the linear layers
    k0a_kernel<<<(2 * H + 7) / 8, 256>>>(Wcn, Wf, ws);
    k0b_kernel<<<(H + 3 + 7) / 8, 256>>>(Wlin, blin, bcn, bf, ws, bs);
    // 3) fused: adjacency pack (DRAM) + tensor-core edge GEMM + s2 GEMV
    {
        int nbGemm = E / 64;                              // 128
        int nbS2   = N / 8;                               // 1024
        int nbPack = (int)((long long)N * N / 1024 / 8);  // 8192
        int total = nbGemm + nbS2 + nbPack;               // 9344
        fused_kernel<<<total, 256>>>(x, adj, tei, bi, bj, N, E);
    }
    // 4) per-edge: CN bit-AND gather + combine + softplus
    edge_kernel<<<(E + 7) / 8, 256>>>(tei, E, nwords, beta, boolen, out);
}